// round 1
// baseline (speedup 1.0000x reference)
#include <cuda_runtime.h>

#define Nn 2048
#define Ff 32
#define Ee 16
#define Kk 32

// Scratch (device globals — no allocation allowed)
__device__ float g_u[Nn * Ff];    // node_part + b_ne
__device__ float g_pre[Nn * Ff];  // (1+eps) * relu(nodes@W_n + b_n)

// Kernel A: per-node precompute. 65536 threads, one per (j,f).
__global__ void prep_kernel(const float* __restrict__ nodes,
                            const float* __restrict__ W_ne,
                            const float* __restrict__ b_ne,
                            const float* __restrict__ W_n,
                            const float* __restrict__ b_n,
                            const float* __restrict__ eps) {
    int t = blockIdx.x * blockDim.x + threadIdx.x;  // 0..N*F-1
    int j = t >> 5;
    int f = t & 31;
    const float* nrow = nodes + j * Ff;
    float s1 = 0.f, s2 = 0.f;
#pragma unroll
    for (int c = 0; c < Ff; c++) {
        float nv = nrow[c];
        s1 = fmaf(nv, W_ne[c * Ff + f], s1);  // node part of W_ne (rows [0,F))
        s2 = fmaf(nv, W_n[c * Ff + f], s2);
    }
    g_u[t] = s1 + b_ne[f];
    g_pre[t] = (1.0f + eps[0]) * fmaxf(s2 + b_n[f], 0.f);
}

// Kernel B: one block per row i. 8 warps partition the j dimension.
// Fuses: adj read + adj->out copy, sparse edge matmul + relu + masked sum,
// (1+eps)*node_term add, and the final 32x32 FC + relu.
__global__ __launch_bounds__(256) void main_kernel(
    const float* __restrict__ adj,
    const float* __restrict__ edges,
    const float* __restrict__ W_ne,
    const float* __restrict__ W_net,
    const float* __restrict__ b_net,
    float* __restrict__ out_adj,
    float* __restrict__ out_y) {
    int i = blockIdx.x;
    int lane = threadIdx.x & 31;
    int w = threadIdx.x >> 5;  // warp 0..7

    // Lane f holds column f of the edge-part weights W_ne[F:, f] (16 regs).
    float we[Ee];
#pragma unroll
    for (int e = 0; e < Ee; e++) we[e] = W_ne[(Ff + e) * Ff + lane];

    const float* adjrow = adj + (size_t)i * Nn;
    float* oadj = out_adj + (size_t)i * Nn;
    const float* erow = edges + (size_t)i * Nn * Ee;

    float msg = 0.f;

    // Each warp scans j in 32-wide coalesced chunks, strided by 8 warps.
    for (int jb = w * 32; jb < Nn; jb += 8 * 32) {
        float a = adjrow[jb + lane];
        oadj[jb + lane] = a;  // fused adj pass-through copy
        unsigned mask = __ballot_sync(0xffffffffu, a != 0.f);
        while (mask) {
            int b = __ffs(mask) - 1;
            mask &= mask - 1;
            int j = jb + b;
            float av = __shfl_sync(0xffffffffu, a, b);
            // All 32 lanes broadcast-load the 16-float edge vector (4x float4).
            const float4* ep =
                reinterpret_cast<const float4*>(erow + (size_t)j * Ee);
            float4 e0 = ep[0], e1 = ep[1], e2 = ep[2], e3 = ep[3];
            float s;
            s = e0.x * we[0];
            s = fmaf(e0.y, we[1], s);
            s = fmaf(e0.z, we[2], s);
            s = fmaf(e0.w, we[3], s);
            s = fmaf(e1.x, we[4], s);
            s = fmaf(e1.y, we[5], s);
            s = fmaf(e1.z, we[6], s);
            s = fmaf(e1.w, we[7], s);
            s = fmaf(e2.x, we[8], s);
            s = fmaf(e2.y, we[9], s);
            s = fmaf(e2.z, we[10], s);
            s = fmaf(e2.w, we[11], s);
            s = fmaf(e3.x, we[12], s);
            s = fmaf(e3.y, we[13], s);
            s = fmaf(e3.z, we[14], s);
            s = fmaf(e3.w, we[15], s);
            float ne = fmaxf(s + g_u[j * Ff + lane], 0.f);
            msg = fmaf(av, ne, msg);  // adj entries are 0/1; multiply is safe
        }
    }

    __shared__ float smsg[8][33];
    smsg[w][lane] = msg;
    __syncthreads();

    if (w == 0) {
        float m = 0.f;
#pragma unroll
        for (int k = 0; k < 8; k++) m += smsg[k][lane];
        float p = g_pre[i * Ff + lane] + m;  // (1+eps)*node_term + msg
        // Epilogue FC: out[k] = relu(sum_f p[f] * W_net[f,k] + b_net[k])
        float acc = b_net[lane];
#pragma unroll
        for (int f = 0; f < Ff; f++)
            acc = fmaf(__shfl_sync(0xffffffffu, p, f), W_net[f * Kk + lane],
                       acc);
        out_y[(size_t)i * Kk + lane] = fmaxf(acc, 0.f);
    }
}

extern "C" void kernel_launch(void* const* d_in, const int* in_sizes, int n_in,
                              void* d_out, int out_size) {
    const float* adj = (const float*)d_in[0];
    const float* nodes = (const float*)d_in[1];
    const float* edges = (const float*)d_in[2];
    const float* W_ne = (const float*)d_in[3];
    const float* b_ne = (const float*)d_in[4];
    const float* W_n = (const float*)d_in[5];
    const float* b_n = (const float*)d_in[6];
    const float* W_net = (const float*)d_in[7];
    const float* b_net = (const float*)d_in[8];
    const float* eps = (const float*)d_in[9];

    float* out = (float*)d_out;
    float* out_adj = out;                                       // [N,N]
    float* out_y = out + (size_t)Nn * Nn;                       // [N,K]
    float* out_edges = out + (size_t)Nn * Nn + (size_t)Nn * Kk; // [N,N,E]

    // Bulk pass-through of edges_features (256 MB, D2D, capture-safe).
    cudaMemcpyAsync(out_edges, edges, (size_t)Nn * Nn * Ee * sizeof(float),
                    cudaMemcpyDeviceToDevice, 0);

    prep_kernel<<<(Nn * Ff) / 256, 256>>>(nodes, W_ne, b_ne, W_n, b_n, eps);
    main_kernel<<<Nn, 256>>>(adj, edges, W_ne, W_net, b_net, out_adj, out_y);
}

// round 3
// speedup vs baseline: 1.1604x; 1.1604x over previous
#include <cuda_runtime.h>

#define Nn 2048
#define Ff 32
#define Ee 16
#define Kk 32

// Scratch (device globals — no allocation allowed)
__device__ float g_u[Nn * Ff];    // node_part + b_ne
__device__ float g_pre[Nn * Ff];  // (1+eps) * relu(nodes@W_n + b_n)

// Kernel A: per-node precompute. 65536 threads, one per (j,f).
__global__ void prep_kernel(const float* __restrict__ nodes,
                            const float* __restrict__ W_ne,
                            const float* __restrict__ b_ne,
                            const float* __restrict__ W_n,
                            const float* __restrict__ b_n,
                            const float* __restrict__ eps) {
    int t = blockIdx.x * blockDim.x + threadIdx.x;  // 0..N*F-1
    int j = t >> 5;
    int f = t & 31;
    const float* nrow = nodes + j * Ff;
    float s1 = 0.f, s2 = 0.f;
#pragma unroll
    for (int c = 0; c < Ff; c++) {
        float nv = nrow[c];
        s1 = fmaf(nv, W_ne[c * Ff + f], s1);  // node part of W_ne (rows [0,F))
        s2 = fmaf(nv, W_n[c * Ff + f], s2);
    }
    g_u[t] = s1 + b_ne[f];
    g_pre[t] = (1.0f + eps[0]) * fmaxf(s2 + b_n[f], 0.f);
}

// Fused kernel: one block per row i.
// Phase 1: copy edges[i] row (128 KB) -> out_edges, coalesced float4, high MLP.
//          This is the bulk of all HBM traffic AND warms L2 for phase 2.
// Phase 2: adj read + adj->out copy, sparse edge matmul + relu + masked sum
//          (edge reads now hit L2), then (1+eps)*node_term add and the
//          final 32x32 FC + relu.
__global__ __launch_bounds__(256) void fused_kernel(
    const float* __restrict__ adj,
    const float* __restrict__ edges,
    const float* __restrict__ W_ne,
    const float* __restrict__ W_net,
    const float* __restrict__ b_net,
    float* __restrict__ out_adj,
    float* __restrict__ out_y,
    float* __restrict__ out_edges) {
    int i = blockIdx.x;
    int t = threadIdx.x;
    int lane = t & 31;
    int w = t >> 5;  // warp 0..7

    const float* erow = edges + (size_t)i * Nn * Ee;
    const float4* erow4 = reinterpret_cast<const float4*>(erow);
    float4* oe4 = reinterpret_cast<float4*>(out_edges + (size_t)i * Nn * Ee);

    // ---- Phase 1: bulk copy of this row's edge features ----
    // 2048*16 floats = 8192 float4; 256 threads -> 32 each, 8-wide batches.
    for (int r = 0; r < 4; r++) {
        float4 v0, v1, v2, v3, v4, v5, v6, v7;
        int base = t + r * 8 * 256;
        v0 = erow4[base + 0 * 256];
        v1 = erow4[base + 1 * 256];
        v2 = erow4[base + 2 * 256];
        v3 = erow4[base + 3 * 256];
        v4 = erow4[base + 4 * 256];
        v5 = erow4[base + 5 * 256];
        v6 = erow4[base + 6 * 256];
        v7 = erow4[base + 7 * 256];
        oe4[base + 0 * 256] = v0;
        oe4[base + 1 * 256] = v1;
        oe4[base + 2 * 256] = v2;
        oe4[base + 3 * 256] = v3;
        oe4[base + 4 * 256] = v4;
        oe4[base + 5 * 256] = v5;
        oe4[base + 6 * 256] = v6;
        oe4[base + 7 * 256] = v7;
    }

    // ---- Phase 2: sparse message computation ----
    // Lane f holds column f of the edge-part weights W_ne[F:, f] (16 regs).
    float we[Ee];
#pragma unroll
    for (int e = 0; e < Ee; e++) we[e] = W_ne[(Ff + e) * Ff + lane];

    const float* adjrow = adj + (size_t)i * Nn;
    float* oadj = out_adj + (size_t)i * Nn;

    float msg = 0.f;

    // Each warp scans j in 32-wide coalesced chunks, strided by 8 warps.
    for (int jb = w * 32; jb < Nn; jb += 8 * 32) {
        float a = adjrow[jb + lane];
        oadj[jb + lane] = a;  // fused adj pass-through copy
        unsigned mask = __ballot_sync(0xffffffffu, a != 0.f);
        while (mask) {
            int b = __ffs(mask) - 1;
            mask &= mask - 1;
            int j = jb + b;
            float av = __shfl_sync(0xffffffffu, a, b);
            // All 32 lanes broadcast-load the 16-float edge vector (L2-hot).
            const float4* ep = erow4 + (size_t)j * 4;
            float4 e0 = ep[0], e1 = ep[1], e2 = ep[2], e3 = ep[3];
            float s;
            s = e0.x * we[0];
            s = fmaf(e0.y, we[1], s);
            s = fmaf(e0.z, we[2], s);
            s = fmaf(e0.w, we[3], s);
            s = fmaf(e1.x, we[4], s);
            s = fmaf(e1.y, we[5], s);
            s = fmaf(e1.z, we[6], s);
            s = fmaf(e1.w, we[7], s);
            s = fmaf(e2.x, we[8], s);
            s = fmaf(e2.y, we[9], s);
            s = fmaf(e2.z, we[10], s);
            s = fmaf(e2.w, we[11], s);
            s = fmaf(e3.x, we[12], s);
            s = fmaf(e3.y, we[13], s);
            s = fmaf(e3.z, we[14], s);
            s = fmaf(e3.w, we[15], s);
            float ne = fmaxf(s + g_u[j * Ff + lane], 0.f);
            msg = fmaf(av, ne, msg);  // adj entries are 0/1
        }
    }

    __shared__ float smsg[8][33];
    smsg[w][lane] = msg;
    __syncthreads();

    if (w == 0) {
        float m = 0.f;
#pragma unroll
        for (int k = 0; k < 8; k++) m += smsg[k][lane];
        float p = g_pre[i * Ff + lane] + m;  // (1+eps)*node_term + msg
        // Epilogue FC: out[k] = relu(sum_f p[f] * W_net[f,k] + b_net[k])
        float acc = b_net[lane];
#pragma unroll
        for (int f = 0; f < Ff; f++)
            acc = fmaf(__shfl_sync(0xffffffffu, p, f), W_net[f * Kk + lane],
                       acc);
        out_y[(size_t)i * Kk + lane] = fmaxf(acc, 0.f);
    }
}

extern "C" void kernel_launch(void* const* d_in, const int* in_sizes, int n_in,
                              void* d_out, int out_size) {
    const float* adj = (const float*)d_in[0];
    const float* nodes = (const float*)d_in[1];
    const float* edges = (const float*)d_in[2];
    const float* W_ne = (const float*)d_in[3];
    const float* b_ne = (const float*)d_in[4];
    const float* W_n = (const float*)d_in[5];
    const float* b_n = (const float*)d_in[6];
    const float* W_net = (const float*)d_in[7];
    const float* b_net = (const float*)d_in[8];
    const float* eps = (const float*)d_in[9];

    float* out = (float*)d_out;
    float* out_adj = out;                                       // [N,N]
    float* out_y = out + (size_t)Nn * Nn;                       // [N,K]
    float* out_edges = out + (size_t)Nn * Nn + (size_t)Nn * Kk; // [N,N,E]

    prep_kernel<<<(Nn * Ff) / 256, 256>>>(nodes, W_ne, b_ne, W_n, b_n, eps);
    fused_kernel<<<Nn, 256>>>(adj, edges, W_ne, W_net, b_net, out_adj, out_y,
                              out_edges);
}